// round 14
// baseline (speedup 1.0000x reference)
#include <cuda_runtime.h>
#include <cstdint>

#define SS 30
#define SP 900          // 30*30
#define S4 810000       // 30^4
#define NB 2

typedef unsigned long long ull;

// t1: [b][br][cipair5][h1w1][pos][2]  (lanes = ci even/odd)  — float2 elements
__device__ __align__(16) float g_t1[NB * 2 * 5 * SP * SP * 2];
// t2: [b][co10][h1w1][pos][br2]  — float2 elements (lanes = branch A/B)
__device__ __align__(16) float g_t2[NB * 10 * SP * SP * 2];
// Weights
__device__ __align__(16) float g_W1[9 * 9 * 20];                 // [to][ti][co20]
// W2: [br][to][cp][ti][cohalf][co5+pad][ci-lane]  (12 ull per tap, 16B-aligned)
__device__ __align__(16) float g_W2[2 * 9 * 5 * 9 * 12 * 2];
__device__ __align__(16) float g_W3[9 * 10 * 9 * 2];             // [to][ci][ti][br2]

#define PACK2(d, a, b)  asm("mov.b64 %0, {%1, %2};" : "=l"(d) : "f"(a), "f"(b))
#define FMA2(d, a, b)   asm("fma.rn.f32x2 %0, %1, %2, %0;" : "+l"(d) : "l"(a), "l"(b))
#define ADD2(d, a, b)   asm("add.rn.f32x2 %0, %1, %2;" : "=l"(d) : "l"(a), "l"(b))
#define UNPACK2(lo, hi, d) asm("mov.b64 {%0, %1}, %2;" : "=f"(lo), "=f"(hi) : "l"(d))

__device__ __forceinline__ uint32_t s2u(const void* p) {
    uint32_t a;
    asm("{ .reg .u64 t; cvta.to.shared.u64 t, %1; cvt.u32.u64 %0, t; }"
        : "=r"(a) : "l"(p));
    return a;
}
__device__ __forceinline__ void cpa4(uint32_t s, const void* g, int srcsz) {
    asm volatile("cp.async.ca.shared.global [%0], [%1], 4, %2;"
                 :: "r"(s), "l"(g), "r"(srcsz));
}
__device__ __forceinline__ void cpa16(uint32_t s, const void* g, int srcsz) {
    asm volatile("cp.async.ca.shared.global [%0], [%1], 16, %2;"
                 :: "r"(s), "l"(g), "r"(srcsz));
}
__device__ __forceinline__ void cpa_commit() {
    asm volatile("cp.async.commit_group;");
}
__device__ __forceinline__ void cpa_commit_wait() {
    asm volatile("cp.async.commit_group;");
    asm volatile("cp.async.wait_group 0;" ::: "memory");
}
__device__ __forceinline__ void cpa_wait1() {
    asm volatile("cp.async.wait_group 1;" ::: "memory");
}

// ---------------------------------------------------------------------------
// Weight prep.
// ---------------------------------------------------------------------------
__global__ void prep_kernel(const float* __restrict__ w1,
                            const float* __restrict__ w2,
                            const float* __restrict__ w3) {
    int tid = blockIdx.x * blockDim.x + threadIdx.x;
    int stride = gridDim.x * blockDim.x;
    for (int i = tid; i < 9 * 9 * 20; i += stride) {
        int co = i % 20;
        int ti = (i / 20) % 9;
        int to = i / 180;
        g_W1[i] = (co < 10) ? w1[co * 81 + to * 9 + ti]
                            : w1[(co - 10) * 81 + ti * 9 + to];
    }
    // W2 padded: j = [br][to][cp][ti][half][co6], lane = ci parity
    for (int i = tid; i < 19440; i += stride) {
        int lane = i & 1;
        int j = i >> 1;
        int co6 = j % 6;
        int half = (j / 6) % 2;
        int ti = (j / 12) % 9;
        int cp = (j / 108) % 5;
        int to = (j / 540) % 9;
        int br = j / 4860;
        float v = 0.f;
        if (co6 < 5) {
            int co = half * 5 + co6;
            int ci = 2 * cp + lane;
            int tap = br ? (ti * 9 + to) : (to * 9 + ti);
            v = w2[(co * 10 + ci) * 81 + tap];
        }
        g_W2[i] = v;
    }
    for (int i = tid; i < 1620; i += stride) {
        int br = i % 2;
        int ti = (i / 2) % 9;
        int ci = (i / 18) % 10;
        int to = i / 180;
        g_W3[i] = (br == 0) ? w3[ci * 81 + to * 9 + ti]
                            : w3[ci * 81 + ti * 9 + to];
    }
}

// ---------------------------------------------------------------------------
// conv1: x (1 ch) -> t1 (ci-pair interleaved), relu.  One CTA per (b,h1,w1).
// Double-buffered plane staging (round-10 version, passed).
// ---------------------------------------------------------------------------
__global__ __launch_bounds__(300)
void conv1_kernel(const float* __restrict__ x, const float* __restrict__ b1) {
    __shared__ __align__(16) float sIn[2][32 * 33];
    __shared__ __align__(16) float sW[9 * 9 * 20];
    __shared__ float sB[20];
    int bid = blockIdx.x;
    int b = bid / SP;
    int rem = bid % SP;
    int h1 = rem / SS, w1 = rem % SS;
    int tid = threadIdx.x;

    {
        const float4* src = (const float4*)g_W1;
        float4* dst = (float4*)sW;
        for (int i = tid; i < 405; i += 300) dst[i] = src[i];
    }
    if (tid < 20) sB[tid] = b1[tid % 10];
    for (int i = tid; i < 2 * 32 * 33; i += 300) ((float*)sIn)[i] = 0.f;

    int h2 = tid / 10;
    int w2_0 = (tid % 10) * 3;

    int gOff[3], sOff[3];
#pragma unroll
    for (int k = 0; k < 3; k++) {
        int j = tid + k * 300;
        int rr = j / SS, cc = j % SS;
        gOff[k] = j;
        sOff[k] = (rr + 1) * 33 + cc + 1;
    }
    uint32_t sInA = s2u(sIn);
    const float* xb = x + (size_t)b * S4;

    ull acc[10][3];
#pragma unroll
    for (int c = 0; c < 10; c++)
#pragma unroll
        for (int p = 0; p < 3; p++) acc[c][p] = 0ull;

    __syncthreads();

#define C1_STAGE(sarg_, bufarg_)                                               \
    do {                                                                       \
        int st_ = (sarg_);                                                     \
        if (st_ < 9) {                                                         \
            int H_ = h1 + st_ / 3 - 1, W_ = w1 + st_ % 3 - 1;                  \
            bool ok_ = ((unsigned)H_ < SS) && ((unsigned)W_ < SS);             \
            int ssz_ = ok_ ? 4 : 0;                                            \
            const float* pl_ = xb + (ok_ ? (H_ * SS + W_) * SP : 0);           \
            uint32_t d_ = sInA + (uint32_t)(bufarg_) * (1056 * 4);             \
            cpa4(d_ + sOff[0] * 4, pl_ + gOff[0], ssz_);                       \
            cpa4(d_ + sOff[1] * 4, pl_ + gOff[1], ssz_);                       \
            cpa4(d_ + sOff[2] * 4, pl_ + gOff[2], ssz_);                       \
        }                                                                      \
        cpa_commit();                                                          \
    } while (0)

    C1_STAGE(0, 0);
    C1_STAGE(1, 1);

#pragma unroll 1
    for (int to = 0; to < 9; to++) {
        cpa_wait1();
        __syncthreads();
        const float* sbuf = sIn[to & 1];
#pragma unroll
        for (int dh2 = 0; dh2 < 3; dh2++) {
            const float* row = &sbuf[(h2 + dh2) * 33 + w2_0];
            ull dup[5];
#pragma unroll
            for (int j = 0; j < 5; j++) { float v = row[j]; PACK2(dup[j], v, v); }
#pragma unroll
            for (int dw2 = 0; dw2 < 3; dw2++) {
                const ull* wp = (const ull*)(sW + (to * 9 + dh2 * 3 + dw2) * 20);
#pragma unroll
                for (int c = 0; c < 10; c++) {
                    ull w = wp[c];
#pragma unroll
                    for (int p = 0; p < 3; p++) FMA2(acc[c][p], dup[p + dw2], w);
                }
            }
        }
        __syncthreads();
        C1_STAGE(to + 2, to & 1);
    }
#undef C1_STAGE

#pragma unroll
    for (int c = 0; c < 10; c++) {
        int br = c / 5, cp = c % 5;
        float b0 = sB[2 * c], b1v = sB[2 * c + 1];
        float2* d = (float2*)g_t1 +
                    (((size_t)(b * 2 + br) * 5 + cp) * SP + h1 * SS + w1) * SP +
                    h2 * SS + w2_0;
#pragma unroll
        for (int p = 0; p < 3; p++) {
            float lo, hi;
            UNPACK2(lo, hi, acc[c][p]);
            lo += b0; hi += b1v;
            d[p] = make_float2(lo > 0.f ? lo : 0.f, hi > 0.f ? hi : 0.f);
        }
    }
}

// ---------------------------------------------------------------------------
// conv2: t1 (ci-pair float2) -> t2 (branch-interleaved), relu.
// One CTA per (b, br, h1, w1).  150 threads = cohalf(2) x (15 h2grp x 5 w2grp).
// Thread tile 2h2 x 6w2 x 5co — 4 rows loaded once feed both output rows
// (the round-7 conv3 transform applied to conv2).  Same staging/weight
// layout as the round-10 conv2 (passed); tap order per output unchanged.
// ---------------------------------------------------------------------------
__global__ __launch_bounds__(150, 2)
void conv2_kernel(const float* __restrict__ b2) {
    extern __shared__ __align__(16) char sm2[];
    ull* sIn = (ull*)sm2;                       // 5 * 1088 ull
    float* sW = (float*)(sm2 + 5 * 1088 * 8);   // 9720 floats (padded)
    __shared__ float sB[10];

    int bid = blockIdx.x;
    int w1 = bid % SS;
    int t = bid / SS;
    int h1 = t % SS;
    t /= SS;
    int br = t & 1;
    int b = t >> 1;
    int tid = threadIdx.x;

    {
        const float4* src = (const float4*)(g_W2 + br * 9720);
        float4* dst = (float4*)sW;
        for (int i = tid; i < 2430; i += 150) dst[i] = src[i];
    }
    if (tid < 10) sB[tid] = b2[tid];
    for (int i = tid; i < 5440; i += 150) sIn[i] = 0ull;

    int cohalf = tid / 75;
    int pos75 = tid % 75;
    int h2 = (pos75 / 5) * 2;
    int w2_0 = (pos75 % 5) * 6;
    int co0 = cohalf * 5;
    int co6 = cohalf * 6;   // padded weight half offset (ull)

    // staging: 30 threads per plane; plane scp = tid/30, t30 = tid%30;
    // chunk c = t30 + 30k (k<15): f2 off 2c, row 2k + t30/15, col (2t30)%30.
    int scp = tid / 30;
    int t30 = tid % 30;
    uint32_t sBase = s2u(sIn) +
                     (uint32_t)(scp * 1088 + (t30 / 15 + 1) * 34 + 2 +
                                (2 * t30) % 30) * 8;
    const float2* t1f2 = (const float2*)g_t1 + (size_t)(b * 2 + br) * 5 * (size_t)S4;
    size_t gBase = (size_t)scp * S4 + 2 * t30;

    ull acc0[5][6], acc1[5][6];
#pragma unroll
    for (int c = 0; c < 5; c++)
#pragma unroll
        for (int p = 0; p < 6; p++) { acc0[c][p] = 0ull; acc1[c][p] = 0ull; }

#pragma unroll 1
    for (int to = 0; to < 9; to++) {
        int H = h1 + to / 3 - 1, W = w1 + to % 3 - 1;
        bool ok = ((unsigned)H < SS) && ((unsigned)W < SS);
        int srcsz = ok ? 16 : 0;
        size_t poff = ok ? (size_t)(H * SS + W) * SP : 0;
        __syncthreads();
        const float2* g = t1f2 + gBase + poff;
#pragma unroll
        for (int k = 0; k < 15; k++)
            cpa16(sBase + k * (68 * 8), g + k * 60, srcsz);
        cpa_commit_wait();
        __syncthreads();
#pragma unroll 1
        for (int cp = 0; cp < 5; cp++) {
            const ull* rbase = sIn + cp * 1088 + h2 * 34 + w2_0;
            const ull* wbase = (const ull*)sW + (to * 5 + cp) * 108;
#pragma unroll
            for (int rr = 0; rr < 4; rr++) {
                const ulonglong2* rp2 = (const ulonglong2*)(rbase + rr * 34);
                ulonglong2 v0 = rp2[0], v1 = rp2[1], v2 = rp2[2], v3 = rp2[3],
                           v4 = rp2[4];
                ull aw[8] = {v0.y, v1.x, v1.y, v2.x, v2.y, v3.x, v3.y, v4.x};
                if (rr < 3) {
#pragma unroll
                    for (int dw2 = 0; dw2 < 3; dw2++) {
                        const ull* wp = wbase + (rr * 3 + dw2) * 12 + co6;
                        ulonglong2 wA = *(const ulonglong2*)wp;
                        ulonglong2 wB = *(const ulonglong2*)(wp + 2);
                        ull w4 = wp[4];
                        ull wv[5] = {wA.x, wA.y, wB.x, wB.y, w4};
#pragma unroll
                        for (int c = 0; c < 5; c++) {
                            ull w = wv[c];
#pragma unroll
                            for (int p = 0; p < 6; p++)
                                FMA2(acc0[c][p], aw[p + dw2], w);
                        }
                    }
                }
                if (rr > 0) {
#pragma unroll
                    for (int dw2 = 0; dw2 < 3; dw2++) {
                        const ull* wp = wbase + ((rr - 1) * 3 + dw2) * 12 + co6;
                        ulonglong2 wA = *(const ulonglong2*)wp;
                        ulonglong2 wB = *(const ulonglong2*)(wp + 2);
                        ull w4 = wp[4];
                        ull wv[5] = {wA.x, wA.y, wB.x, wB.y, w4};
#pragma unroll
                        for (int c = 0; c < 5; c++) {
                            ull w = wv[c];
#pragma unroll
                            for (int p = 0; p < 6; p++)
                                FMA2(acc1[c][p], aw[p + dw2], w);
                        }
                    }
                }
            }
        }
    }

    int pos0 = h2 * SS + w2_0;
#pragma unroll
    for (int c = 0; c < 5; c++) {
        int co = co0 + c;
        float bias = sB[co];
        float* d = g_t2 + ((size_t)(b * 10 + co) * SP + h1 * SS + w1) * 1800 +
                   pos0 * 2 + br;
#pragma unroll
        for (int p = 0; p < 6; p++) {
            float lo, hi;
            UNPACK2(lo, hi, acc0[c][p]);    // even-ci + odd-ci partials
            float v = lo + hi + bias;
            d[2 * p] = v > 0.f ? v : 0.f;
            UNPACK2(lo, hi, acc1[c][p]);
            v = lo + hi + bias;
            d[60 + 2 * p] = v > 0.f ? v : 0.f;   // row h2+1: +30 positions
        }
    }
}

// ---------------------------------------------------------------------------
// conv3 + final sum: t2 (10 ci, branch-interleaved float2) -> out.
// PAIRED (round-12 version, passed): one CTA per (b, h1, w1-pair).
// ---------------------------------------------------------------------------
__global__ __launch_bounds__(300, 2)
void conv3_kernel(const float* __restrict__ b3, float* __restrict__ out) {
    extern __shared__ __align__(16) char sm3[];
    ull* sD = (ull*)sm3;                        // 10 * 1088 ull
    ull* sW3 = (ull*)(sm3 + 10 * 1088 * 8);     // 810 (wA,wB)

    int bid = blockIdx.x;
    int b = bid / 450;
    int rem = bid % 450;
    int h1 = rem / 15;
    int w1b = (rem % 15) * 2;
    int tid = threadIdx.x;

    for (int i = tid; i < 810; i += 300) sW3[i] = ((const ull*)g_W3)[i];
    for (int i = tid; i < 10880; i += 300) sD[i] = 0ull;

    int P = tid / 150;          // position within pair
    int t150 = tid % 150;
    int cihalf = t150 / 75;
    int pos75 = t150 % 75;
    int h2 = (pos75 / 5) * 2;
    int w2_0 = (pos75 % 5) * 6;
    int ci0 = cihalf * 5;

    int sci = tid / 30;
    int t30 = tid % 30;
    uint32_t sBase = s2u(sD) +
                     (uint32_t)(sci * 1088 + (t30 / 15 + 1) * 34 + 2 +
                                (2 * t30) % 30) * 8;
    const float2* tb2 = (const float2*)g_t2 + (size_t)b * 10 * (size_t)S4;
    size_t gBase = (size_t)sci * S4 + 2 * t30;

    ull acc0[6], acc1[6];
#pragma unroll
    for (int p = 0; p < 6; p++) { acc0[p] = 0ull; acc1[p] = 0ull; }

#pragma unroll 1
    for (int dh1 = 0; dh1 < 3; dh1++) {
        int H = h1 + dh1 - 1;
#pragma unroll 1
        for (int i = 0; i < 4; i++) {
            int W = w1b + i - 1;
            bool ok = ((unsigned)H < SS) && ((unsigned)W < SS);
            int srcsz = ok ? 16 : 0;
            size_t poff = ok ? (size_t)(H * SS + W) * SP : 0;
            __syncthreads();
            const float2* g = tb2 + gBase + poff;
#pragma unroll
            for (int k = 0; k < 15; k++)
                cpa16(sBase + k * (68 * 8), g + k * 60, srcsz);
            cpa_commit_wait();
            __syncthreads();
            int dw1 = i - P;
            if ((unsigned)dw1 < 3u) {
                int to = dh1 * 3 + dw1;
#pragma unroll 1
                for (int cc = 0; cc < 5; cc++) {
                    int ci = ci0 + cc;
                    const ull* rbase = sD + ci * 1088 + h2 * 34 + w2_0;
                    const ull* wci = sW3 + (to * 10 + ci) * 9;
#pragma unroll
                    for (int rr = 0; rr < 4; rr++) {
                        const ulonglong2* rp2 =
                            (const ulonglong2*)(rbase + rr * 34);
                        ulonglong2 v0 = rp2[0], v1 = rp2[1], v2 = rp2[2],
                                   v3 = rp2[3], v4 = rp2[4];
                        ull aw[8] = {v0.y, v1.x, v1.y, v2.x,
                                     v2.y, v3.x, v3.y, v4.x};
                        if (rr < 3) {
#pragma unroll
                            for (int dw2 = 0; dw2 < 3; dw2++) {
                                ull w = wci[rr * 3 + dw2];
#pragma unroll
                                for (int p = 0; p < 6; p++)
                                    FMA2(acc0[p], aw[p + dw2], w);
                            }
                        }
                        if (rr > 0) {
#pragma unroll
                            for (int dw2 = 0; dw2 < 3; dw2++) {
                                ull w = wci[(rr - 1) * 3 + dw2];
#pragma unroll
                                for (int p = 0; p < 6; p++)
                                    FMA2(acc1[p], aw[p + dw2], w);
                            }
                        }
                    }
                }
            }
        }
    }

    // reduce ci-halves via smem (reuse sD); each position independent
    __syncthreads();
    ull* red = (ull*)sD;
    int rbase2 = (P * 75 + pos75) * 12;
    if (cihalf) {
#pragma unroll
        for (int p = 0; p < 6; p++) {
            red[rbase2 + p] = acc0[p];
            red[rbase2 + 6 + p] = acc1[p];
        }
    }
    __syncthreads();
    if (!cihalf) {
        float bv = b3[0];
        int w1p = w1b + P;
        float* dst = out + (size_t)b * S4 + (h1 * SS + w1p) * SP + h2 * SS + w2_0;
#pragma unroll
        for (int p = 0; p < 6; p++) {
            ull o0 = red[rbase2 + p];
            ull o1 = red[rbase2 + 6 + p];
            ADD2(acc0[p], acc0[p], o0);
            ADD2(acc1[p], acc1[p], o1);
            float lo, hi;
            UNPACK2(lo, hi, acc0[p]);
            float va = lo + bv, vb = hi + bv;
            va = va > 0.f ? va : 0.f;
            vb = vb > 0.f ? vb : 0.f;
            dst[p] = va + vb;
            UNPACK2(lo, hi, acc1[p]);
            va = lo + bv; vb = hi + bv;
            va = va > 0.f ? va : 0.f;
            vb = vb > 0.f ? vb : 0.f;
            dst[SS + p] = va + vb;
        }
    }
}

// ---------------------------------------------------------------------------
extern "C" void kernel_launch(void* const* d_in, const int* in_sizes, int n_in,
                              void* d_out, int out_size) {
    const float* x = (const float*)d_in[0];
    const float* w1 = (const float*)d_in[1];
    const float* b1 = (const float*)d_in[2];
    const float* w2 = (const float*)d_in[3];
    const float* b2 = (const float*)d_in[4];
    const float* w3 = (const float*)d_in[5];
    const float* b3 = (const float*)d_in[6];
    float* out = (float*)d_out;

    const int smem2 = 5 * 1088 * 8 + 9720 * 4;    // 43520 + 38880 = 82400 B
    const int smem3 = 10 * 1088 * 8 + 810 * 8;    // 93520 B
    cudaFuncSetAttribute(conv2_kernel,
                         cudaFuncAttributeMaxDynamicSharedMemorySize, smem2);
    cudaFuncSetAttribute(conv3_kernel,
                         cudaFuncAttributeMaxDynamicSharedMemorySize, smem3);

    prep_kernel<<<32, 256>>>(w1, w2, w3);
    conv1_kernel<<<NB * SP, 300>>>(x, b1);
    conv2_kernel<<<NB * 2 * SP, 150, smem2>>>(b2);
    conv3_kernel<<<NB * 450, 300, smem3>>>(b3, out);
}

// round 15
// speedup vs baseline: 1.2761x; 1.2761x over previous
#include <cuda_runtime.h>
#include <cstdint>

#define SS 30
#define SP 900          // 30*30
#define S4 810000       // 30^4
#define NB 2

typedef unsigned long long ull;

// t1: [b][br][cipair5][h1w1][pos][2]  (lanes = ci even/odd)  — float2 elements
__device__ __align__(16) float g_t1[NB * 2 * 5 * SP * SP * 2];
// t2: [b][co10][h1w1][pos][br2]  — float2 elements (lanes = branch A/B)
__device__ __align__(16) float g_t2[NB * 10 * SP * SP * 2];
// Weights
__device__ __align__(16) float g_W1[9 * 9 * 20];                 // [to][ti][co20]
// W2: [br][to][cp][ti][cohalf][co5+pad][ci-lane]  (12 ull per tap, 16B-aligned)
__device__ __align__(16) float g_W2[2 * 9 * 5 * 9 * 12 * 2];
__device__ __align__(16) float g_W3[9 * 10 * 9 * 2];             // [to][ci][ti][br2]

#define PACK2(d, a, b)  asm("mov.b64 %0, {%1, %2};" : "=l"(d) : "f"(a), "f"(b))
#define FMA2(d, a, b)   asm("fma.rn.f32x2 %0, %1, %2, %0;" : "+l"(d) : "l"(a), "l"(b))
#define ADD2(d, a, b)   asm("add.rn.f32x2 %0, %1, %2;" : "=l"(d) : "l"(a), "l"(b))
#define UNPACK2(lo, hi, d) asm("mov.b64 {%0, %1}, %2;" : "=f"(lo), "=f"(hi) : "l"(d))

__device__ __forceinline__ uint32_t s2u(const void* p) {
    uint32_t a;
    asm("{ .reg .u64 t; cvta.to.shared.u64 t, %1; cvt.u32.u64 %0, t; }"
        : "=r"(a) : "l"(p));
    return a;
}
__device__ __forceinline__ void cpa4(uint32_t s, const void* g, int srcsz) {
    asm volatile("cp.async.ca.shared.global [%0], [%1], 4, %2;"
                 :: "r"(s), "l"(g), "r"(srcsz));
}
__device__ __forceinline__ void cpa16(uint32_t s, const void* g, int srcsz) {
    asm volatile("cp.async.cg.shared.global [%0], [%1], 16, %2;"
                 :: "r"(s), "l"(g), "r"(srcsz));
}
__device__ __forceinline__ void cpa_commit() {
    asm volatile("cp.async.commit_group;");
}
__device__ __forceinline__ void cpa_commit_wait() {
    asm volatile("cp.async.commit_group;");
    asm volatile("cp.async.wait_group 0;" ::: "memory");
}
__device__ __forceinline__ void cpa_wait1() {
    asm volatile("cp.async.wait_group 1;" ::: "memory");
}

// ---------------------------------------------------------------------------
// Weight prep.
// ---------------------------------------------------------------------------
__global__ void prep_kernel(const float* __restrict__ w1,
                            const float* __restrict__ w2,
                            const float* __restrict__ w3) {
    int tid = blockIdx.x * blockDim.x + threadIdx.x;
    int stride = gridDim.x * blockDim.x;
    for (int i = tid; i < 9 * 9 * 20; i += stride) {
        int co = i % 20;
        int ti = (i / 20) % 9;
        int to = i / 180;
        g_W1[i] = (co < 10) ? w1[co * 81 + to * 9 + ti]
                            : w1[(co - 10) * 81 + ti * 9 + to];
    }
    // W2 padded: j = [br][to][cp][ti][half][co6], lane = ci parity
    for (int i = tid; i < 19440; i += stride) {
        int lane = i & 1;
        int j = i >> 1;
        int co6 = j % 6;
        int half = (j / 6) % 2;
        int ti = (j / 12) % 9;
        int cp = (j / 108) % 5;
        int to = (j / 540) % 9;
        int br = j / 4860;
        float v = 0.f;
        if (co6 < 5) {
            int co = half * 5 + co6;
            int ci = 2 * cp + lane;
            int tap = br ? (ti * 9 + to) : (to * 9 + ti);
            v = w2[(co * 10 + ci) * 81 + tap];
        }
        g_W2[i] = v;
    }
    for (int i = tid; i < 1620; i += stride) {
        int br = i % 2;
        int ti = (i / 2) % 9;
        int ci = (i / 18) % 10;
        int to = i / 180;
        g_W3[i] = (br == 0) ? w3[ci * 81 + to * 9 + ti]
                            : w3[ci * 81 + ti * 9 + to];
    }
}

// ---------------------------------------------------------------------------
// conv1: x (1 ch) -> t1 (ci-pair interleaved), relu.  One CTA per (b,h1,w1).
// Double-buffered plane staging (round-10 version, passed).
// ---------------------------------------------------------------------------
__global__ __launch_bounds__(300)
void conv1_kernel(const float* __restrict__ x, const float* __restrict__ b1) {
    __shared__ __align__(16) float sIn[2][32 * 33];
    __shared__ __align__(16) float sW[9 * 9 * 20];
    __shared__ float sB[20];
    int bid = blockIdx.x;
    int b = bid / SP;
    int rem = bid % SP;
    int h1 = rem / SS, w1 = rem % SS;
    int tid = threadIdx.x;

    {
        const float4* src = (const float4*)g_W1;
        float4* dst = (float4*)sW;
        for (int i = tid; i < 405; i += 300) dst[i] = src[i];
    }
    if (tid < 20) sB[tid] = b1[tid % 10];
    for (int i = tid; i < 2 * 32 * 33; i += 300) ((float*)sIn)[i] = 0.f;

    int h2 = tid / 10;
    int w2_0 = (tid % 10) * 3;

    int gOff[3], sOff[3];
#pragma unroll
    for (int k = 0; k < 3; k++) {
        int j = tid + k * 300;
        int rr = j / SS, cc = j % SS;
        gOff[k] = j;
        sOff[k] = (rr + 1) * 33 + cc + 1;
    }
    uint32_t sInA = s2u(sIn);
    const float* xb = x + (size_t)b * S4;

    ull acc[10][3];
#pragma unroll
    for (int c = 0; c < 10; c++)
#pragma unroll
        for (int p = 0; p < 3; p++) acc[c][p] = 0ull;

    __syncthreads();

#define C1_STAGE(sarg_, bufarg_)                                               \
    do {                                                                       \
        int st_ = (sarg_);                                                     \
        if (st_ < 9) {                                                         \
            int H_ = h1 + st_ / 3 - 1, W_ = w1 + st_ % 3 - 1;                  \
            bool ok_ = ((unsigned)H_ < SS) && ((unsigned)W_ < SS);             \
            int ssz_ = ok_ ? 4 : 0;                                            \
            const float* pl_ = xb + (ok_ ? (H_ * SS + W_) * SP : 0);           \
            uint32_t d_ = sInA + (uint32_t)(bufarg_) * (1056 * 4);             \
            cpa4(d_ + sOff[0] * 4, pl_ + gOff[0], ssz_);                       \
            cpa4(d_ + sOff[1] * 4, pl_ + gOff[1], ssz_);                       \
            cpa4(d_ + sOff[2] * 4, pl_ + gOff[2], ssz_);                       \
        }                                                                      \
        cpa_commit();                                                          \
    } while (0)

    C1_STAGE(0, 0);
    C1_STAGE(1, 1);

#pragma unroll 1
    for (int to = 0; to < 9; to++) {
        cpa_wait1();
        __syncthreads();
        const float* sbuf = sIn[to & 1];
#pragma unroll
        for (int dh2 = 0; dh2 < 3; dh2++) {
            const float* row = &sbuf[(h2 + dh2) * 33 + w2_0];
            ull dup[5];
#pragma unroll
            for (int j = 0; j < 5; j++) { float v = row[j]; PACK2(dup[j], v, v); }
#pragma unroll
            for (int dw2 = 0; dw2 < 3; dw2++) {
                const ull* wp = (const ull*)(sW + (to * 9 + dh2 * 3 + dw2) * 20);
#pragma unroll
                for (int c = 0; c < 10; c++) {
                    ull w = wp[c];
#pragma unroll
                    for (int p = 0; p < 3; p++) FMA2(acc[c][p], dup[p + dw2], w);
                }
            }
        }
        __syncthreads();
        C1_STAGE(to + 2, to & 1);
    }
#undef C1_STAGE

#pragma unroll
    for (int c = 0; c < 10; c++) {
        int br = c / 5, cp = c % 5;
        float b0 = sB[2 * c], b1v = sB[2 * c + 1];
        float2* d = (float2*)g_t1 +
                    (((size_t)(b * 2 + br) * 5 + cp) * SP + h1 * SS + w1) * SP +
                    h2 * SS + w2_0;
#pragma unroll
        for (int p = 0; p < 3; p++) {
            float lo, hi;
            UNPACK2(lo, hi, acc[c][p]);
            lo += b0; hi += b1v;
            d[p] = make_float2(lo > 0.f ? lo : 0.f, hi > 0.f ? hi : 0.f);
        }
    }
}

// ---------------------------------------------------------------------------
// conv2: t1 (ci-pair float2) -> t2 (branch-interleaved), relu.
// Round-10 version (passed, best): 5 planes staged per to, wait0, static
// padded weights, aligned 5xLDS.128 input windows.
// ---------------------------------------------------------------------------
__global__ __launch_bounds__(300, 2)
void conv2_kernel(const float* __restrict__ b2) {
    extern __shared__ __align__(16) char sm2[];
    ull* sIn = (ull*)sm2;                       // 5 * 1088 ull
    float* sW = (float*)(sm2 + 5 * 1088 * 8);   // 9720 floats (padded)
    __shared__ float sB[10];

    int bid = blockIdx.x;
    int w1 = bid % SS;
    int t = bid / SS;
    int h1 = t % SS;
    t /= SS;
    int br = t & 1;
    int b = t >> 1;
    int tid = threadIdx.x;

    {
        const float4* src = (const float4*)(g_W2 + br * 9720);
        float4* dst = (float4*)sW;
        for (int i = tid; i < 2430; i += 300) dst[i] = src[i];
    }
    if (tid < 10) sB[tid] = b2[tid];
    for (int i = tid; i < 5440; i += 300) sIn[i] = 0ull;

    int cohalf = tid / 150;
    int r = tid % 150;
    int h2 = r / 5;
    int w2_0 = (r % 5) * 6;
    int co0 = cohalf * 5;
    int co6 = cohalf * 6;   // padded weight half offset (ull)

    // staging: plane scp = tid/60, t60 = tid%60, chunks t60 + k*60
    int scp = tid / 60;
    int t60 = tid % 60;
    int kmax = (t60 < 30) ? 8 : 7;
    uint32_t sBase = s2u(sIn) +
                     (uint32_t)(scp * 1088 + (t60 / 15 + 1) * 34 + 2 +
                                (2 * t60) % 30) * 8;
    const float2* t1f2 = (const float2*)g_t1 + (size_t)(b * 2 + br) * 5 * (size_t)S4;
    size_t gBase = (size_t)scp * S4 + 2 * t60;

    ull acc[5][6];
#pragma unroll
    for (int c = 0; c < 5; c++)
#pragma unroll
        for (int p = 0; p < 6; p++) acc[c][p] = 0ull;

#pragma unroll 1
    for (int to = 0; to < 9; to++) {
        int H = h1 + to / 3 - 1, W = w1 + to % 3 - 1;
        bool ok = ((unsigned)H < SS) && ((unsigned)W < SS);
        int srcsz = ok ? 16 : 0;
        int poff = ok ? (H * SS + W) : 0;
        __syncthreads();
        const float2* g = t1f2 + gBase + (size_t)poff * SP;
#pragma unroll
        for (int k = 0; k < 8; k++)
            if (k < kmax) cpa16(sBase + k * (136 * 8), g + k * 120, srcsz);
        cpa_commit_wait();
        __syncthreads();
#pragma unroll 1
        for (int cp = 0; cp < 5; cp++) {
            const ull* sc = sIn + cp * 1088;
            const ull* wbase = (const ull*)sW + (to * 5 + cp) * 108;
#pragma unroll
            for (int dh2 = 0; dh2 < 3; dh2++) {
                const ulonglong2* rp2 =
                    (const ulonglong2*)(sc + (h2 + dh2) * 34 + w2_0);
                ulonglong2 v0 = rp2[0], v1 = rp2[1], v2 = rp2[2], v3 = rp2[3],
                           v4 = rp2[4];
                ull aw[8] = {v0.y, v1.x, v1.y, v2.x, v2.y, v3.x, v3.y, v4.x};
#pragma unroll
                for (int dw2 = 0; dw2 < 3; dw2++) {
                    const ull* wp = wbase + (dh2 * 3 + dw2) * 12 + co6;
                    ulonglong2 wA = *(const ulonglong2*)wp;
                    ulonglong2 wB = *(const ulonglong2*)(wp + 2);
                    ull w4 = wp[4];
                    ull wv[5] = {wA.x, wA.y, wB.x, wB.y, w4};
#pragma unroll
                    for (int c = 0; c < 5; c++) {
                        ull w = wv[c];
#pragma unroll
                        for (int p = 0; p < 6; p++) FMA2(acc[c][p], aw[p + dw2], w);
                    }
                }
            }
        }
    }

    int pos0 = h2 * SS + w2_0;
#pragma unroll
    for (int c = 0; c < 5; c++) {
        int co = co0 + c;
        float bias = sB[co];
        float* d = g_t2 + ((size_t)(b * 10 + co) * SP + h1 * SS + w1) * 1800 +
                   pos0 * 2 + br;
#pragma unroll
        for (int p = 0; p < 6; p++) {
            float lo, hi;
            UNPACK2(lo, hi, acc[c][p]);     // even-ci + odd-ci partials
            float v = lo + hi + bias;
            d[2 * p] = v > 0.f ? v : 0.f;
        }
    }
}

// ---------------------------------------------------------------------------
// conv3 + final sum: t2 (10 ci, branch-interleaved float2) -> out.
// PAIRED (round-12 version, passed): one CTA per (b, h1, w1-pair).
// ---------------------------------------------------------------------------
__global__ __launch_bounds__(300, 2)
void conv3_kernel(const float* __restrict__ b3, float* __restrict__ out) {
    extern __shared__ __align__(16) char sm3[];
    ull* sD = (ull*)sm3;                        // 10 * 1088 ull
    ull* sW3 = (ull*)(sm3 + 10 * 1088 * 8);     // 810 (wA,wB)

    int bid = blockIdx.x;
    int b = bid / 450;
    int rem = bid % 450;
    int h1 = rem / 15;
    int w1b = (rem % 15) * 2;
    int tid = threadIdx.x;

    for (int i = tid; i < 810; i += 300) sW3[i] = ((const ull*)g_W3)[i];
    for (int i = tid; i < 10880; i += 300) sD[i] = 0ull;

    int P = tid / 150;          // position within pair
    int t150 = tid % 150;
    int cihalf = t150 / 75;
    int pos75 = t150 % 75;
    int h2 = (pos75 / 5) * 2;
    int w2_0 = (pos75 % 5) * 6;
    int ci0 = cihalf * 5;

    int sci = tid / 30;
    int t30 = tid % 30;
    uint32_t sBase = s2u(sD) +
                     (uint32_t)(sci * 1088 + (t30 / 15 + 1) * 34 + 2 +
                                (2 * t30) % 30) * 8;
    const float2* tb2 = (const float2*)g_t2 + (size_t)b * 10 * (size_t)S4;
    size_t gBase = (size_t)sci * S4 + 2 * t30;

    ull acc0[6], acc1[6];
#pragma unroll
    for (int p = 0; p < 6; p++) { acc0[p] = 0ull; acc1[p] = 0ull; }

#pragma unroll 1
    for (int dh1 = 0; dh1 < 3; dh1++) {
        int H = h1 + dh1 - 1;
#pragma unroll 1
        for (int i = 0; i < 4; i++) {
            int W = w1b + i - 1;
            bool ok = ((unsigned)H < SS) && ((unsigned)W < SS);
            int srcsz = ok ? 16 : 0;
            size_t poff = ok ? (size_t)(H * SS + W) * SP : 0;
            __syncthreads();
            const float2* g = tb2 + gBase + poff;
#pragma unroll
            for (int k = 0; k < 15; k++)
                cpa16(sBase + k * (68 * 8), g + k * 60, srcsz);
            cpa_commit_wait();
            __syncthreads();
            int dw1 = i - P;
            if ((unsigned)dw1 < 3u) {
                int to = dh1 * 3 + dw1;
#pragma unroll 1
                for (int cc = 0; cc < 5; cc++) {
                    int ci = ci0 + cc;
                    const ull* rbase = sD + ci * 1088 + h2 * 34 + w2_0;
                    const ull* wci = sW3 + (to * 10 + ci) * 9;
#pragma unroll
                    for (int rr = 0; rr < 4; rr++) {
                        const ulonglong2* rp2 =
                            (const ulonglong2*)(rbase + rr * 34);
                        ulonglong2 v0 = rp2[0], v1 = rp2[1], v2 = rp2[2],
                                   v3 = rp2[3], v4 = rp2[4];
                        ull aw[8] = {v0.y, v1.x, v1.y, v2.x,
                                     v2.y, v3.x, v3.y, v4.x};
                        if (rr < 3) {
#pragma unroll
                            for (int dw2 = 0; dw2 < 3; dw2++) {
                                ull w = wci[rr * 3 + dw2];
#pragma unroll
                                for (int p = 0; p < 6; p++)
                                    FMA2(acc0[p], aw[p + dw2], w);
                            }
                        }
                        if (rr > 0) {
#pragma unroll
                            for (int dw2 = 0; dw2 < 3; dw2++) {
                                ull w = wci[(rr - 1) * 3 + dw2];
#pragma unroll
                                for (int p = 0; p < 6; p++)
                                    FMA2(acc1[p], aw[p + dw2], w);
                            }
                        }
                    }
                }
            }
        }
    }

    // reduce ci-halves via smem (reuse sD); each position independent
    __syncthreads();
    ull* red = (ull*)sD;
    int rbase2 = (P * 75 + pos75) * 12;
    if (cihalf) {
#pragma unroll
        for (int p = 0; p < 6; p++) {
            red[rbase2 + p] = acc0[p];
            red[rbase2 + 6 + p] = acc1[p];
        }
    }
    __syncthreads();
    if (!cihalf) {
        float bv = b3[0];
        int w1p = w1b + P;
        float* dst = out + (size_t)b * S4 + (h1 * SS + w1p) * SP + h2 * SS + w2_0;
#pragma unroll
        for (int p = 0; p < 6; p++) {
            ull o0 = red[rbase2 + p];
            ull o1 = red[rbase2 + 6 + p];
            ADD2(acc0[p], acc0[p], o0);
            ADD2(acc1[p], acc1[p], o1);
            float lo, hi;
            UNPACK2(lo, hi, acc0[p]);
            float va = lo + bv, vb = hi + bv;
            va = va > 0.f ? va : 0.f;
            vb = vb > 0.f ? vb : 0.f;
            dst[p] = va + vb;
            UNPACK2(lo, hi, acc1[p]);
            va = lo + bv; vb = hi + bv;
            va = va > 0.f ? va : 0.f;
            vb = vb > 0.f ? vb : 0.f;
            dst[SS + p] = va + vb;
        }
    }
}

// ---------------------------------------------------------------------------
extern "C" void kernel_launch(void* const* d_in, const int* in_sizes, int n_in,
                              void* d_out, int out_size) {
    const float* x = (const float*)d_in[0];
    const float* w1 = (const float*)d_in[1];
    const float* b1 = (const float*)d_in[2];
    const float* w2 = (const float*)d_in[3];
    const float* b2 = (const float*)d_in[4];
    const float* w3 = (const float*)d_in[5];
    const float* b3 = (const float*)d_in[6];
    float* out = (float*)d_out;

    const int smem2 = 5 * 1088 * 8 + 9720 * 4;    // 43520 + 38880 = 82400 B
    const int smem3 = 10 * 1088 * 8 + 810 * 8;    // 93520 B
    cudaFuncSetAttribute(conv2_kernel,
                         cudaFuncAttributeMaxDynamicSharedMemorySize, smem2);
    cudaFuncSetAttribute(conv3_kernel,
                         cudaFuncAttributeMaxDynamicSharedMemorySize, smem3);

    prep_kernel<<<32, 256>>>(w1, w2, w3);
    conv1_kernel<<<NB * SP, 300>>>(x, b1);
    conv2_kernel<<<NB * 2 * SP, 300, smem2>>>(b2);
    conv3_kernel<<<NB * 450, 300, smem3>>>(b3, out);
}

// round 16
// speedup vs baseline: 1.3211x; 1.0353x over previous
#include <cuda_runtime.h>
#include <cstdint>

#define SS 30
#define SP 900          // 30*30
#define S4 810000       // 30^4
#define NB 2

typedef unsigned long long ull;

// t1: [b][br][cipair5][h1w1][pos][2]  (lanes = ci even/odd)  — float2 elements
__device__ __align__(16) float g_t1[NB * 2 * 5 * SP * SP * 2];
// t2: [b][co10][h1w1][pos][br2]  — float2 elements (lanes = branch A/B)
__device__ __align__(16) float g_t2[NB * 10 * SP * SP * 2];
// Weights
__device__ __align__(16) float g_W1[9 * 9 * 20];                 // [to][ti][co20]
// W2: [br][to][cp][ti][cohalf][co5+pad][ci-lane]  (12 ull per tap, 16B-aligned)
__device__ __align__(16) float g_W2[2 * 9 * 5 * 9 * 12 * 2];
__device__ __align__(16) float g_W3[9 * 10 * 9 * 2];             // [to][ci][ti][br2]

#define PACK2(d, a, b)  asm("mov.b64 %0, {%1, %2};" : "=l"(d) : "f"(a), "f"(b))
#define FMA2(d, a, b)   asm("fma.rn.f32x2 %0, %1, %2, %0;" : "+l"(d) : "l"(a), "l"(b))
#define ADD2(d, a, b)   asm("add.rn.f32x2 %0, %1, %2;" : "=l"(d) : "l"(a), "l"(b))
#define UNPACK2(lo, hi, d) asm("mov.b64 {%0, %1}, %2;" : "=f"(lo), "=f"(hi) : "l"(d))

__device__ __forceinline__ uint32_t s2u(const void* p) {
    uint32_t a;
    asm("{ .reg .u64 t; cvta.to.shared.u64 t, %1; cvt.u32.u64 %0, t; }"
        : "=r"(a) : "l"(p));
    return a;
}
__device__ __forceinline__ void cpa4(uint32_t s, const void* g, int srcsz) {
    asm volatile("cp.async.ca.shared.global [%0], [%1], 4, %2;"
                 :: "r"(s), "l"(g), "r"(srcsz));
}
// .ca flavor — conv2 staging (L1 allocation helps; R12-verified)
__device__ __forceinline__ void cpa16(uint32_t s, const void* g, int srcsz) {
    asm volatile("cp.async.ca.shared.global [%0], [%1], 16, %2;"
                 :: "r"(s), "l"(g), "r"(srcsz));
}
// .cg flavor — conv3 staging (L1 bypass; R15-verified win for conv3)
__device__ __forceinline__ void cpa16cg(uint32_t s, const void* g, int srcsz) {
    asm volatile("cp.async.cg.shared.global [%0], [%1], 16, %2;"
                 :: "r"(s), "l"(g), "r"(srcsz));
}
__device__ __forceinline__ void cpa_commit() {
    asm volatile("cp.async.commit_group;");
}
__device__ __forceinline__ void cpa_commit_wait() {
    asm volatile("cp.async.commit_group;");
    asm volatile("cp.async.wait_group 0;" ::: "memory");
}
__device__ __forceinline__ void cpa_wait1() {
    asm volatile("cp.async.wait_group 1;" ::: "memory");
}

// ---------------------------------------------------------------------------
// Weight prep.
// ---------------------------------------------------------------------------
__global__ void prep_kernel(const float* __restrict__ w1,
                            const float* __restrict__ w2,
                            const float* __restrict__ w3) {
    int tid = blockIdx.x * blockDim.x + threadIdx.x;
    int stride = gridDim.x * blockDim.x;
    for (int i = tid; i < 9 * 9 * 20; i += stride) {
        int co = i % 20;
        int ti = (i / 20) % 9;
        int to = i / 180;
        g_W1[i] = (co < 10) ? w1[co * 81 + to * 9 + ti]
                            : w1[(co - 10) * 81 + ti * 9 + to];
    }
    // W2 padded: j = [br][to][cp][ti][half][co6], lane = ci parity
    for (int i = tid; i < 19440; i += stride) {
        int lane = i & 1;
        int j = i >> 1;
        int co6 = j % 6;
        int half = (j / 6) % 2;
        int ti = (j / 12) % 9;
        int cp = (j / 108) % 5;
        int to = (j / 540) % 9;
        int br = j / 4860;
        float v = 0.f;
        if (co6 < 5) {
            int co = half * 5 + co6;
            int ci = 2 * cp + lane;
            int tap = br ? (ti * 9 + to) : (to * 9 + ti);
            v = w2[(co * 10 + ci) * 81 + tap];
        }
        g_W2[i] = v;
    }
    for (int i = tid; i < 1620; i += stride) {
        int br = i % 2;
        int ti = (i / 2) % 9;
        int ci = (i / 18) % 10;
        int to = i / 180;
        g_W3[i] = (br == 0) ? w3[ci * 81 + to * 9 + ti]
                            : w3[ci * 81 + ti * 9 + to];
    }
}

// ---------------------------------------------------------------------------
// conv1: x (1 ch) -> t1 (ci-pair interleaved), relu.  One CTA per (b,h1,w1).
// Double-buffered plane staging (round-10 version, passed).
// ---------------------------------------------------------------------------
__global__ __launch_bounds__(300)
void conv1_kernel(const float* __restrict__ x, const float* __restrict__ b1) {
    __shared__ __align__(16) float sIn[2][32 * 33];
    __shared__ __align__(16) float sW[9 * 9 * 20];
    __shared__ float sB[20];
    int bid = blockIdx.x;
    int b = bid / SP;
    int rem = bid % SP;
    int h1 = rem / SS, w1 = rem % SS;
    int tid = threadIdx.x;

    {
        const float4* src = (const float4*)g_W1;
        float4* dst = (float4*)sW;
        for (int i = tid; i < 405; i += 300) dst[i] = src[i];
    }
    if (tid < 20) sB[tid] = b1[tid % 10];
    for (int i = tid; i < 2 * 32 * 33; i += 300) ((float*)sIn)[i] = 0.f;

    int h2 = tid / 10;
    int w2_0 = (tid % 10) * 3;

    int gOff[3], sOff[3];
#pragma unroll
    for (int k = 0; k < 3; k++) {
        int j = tid + k * 300;
        int rr = j / SS, cc = j % SS;
        gOff[k] = j;
        sOff[k] = (rr + 1) * 33 + cc + 1;
    }
    uint32_t sInA = s2u(sIn);
    const float* xb = x + (size_t)b * S4;

    ull acc[10][3];
#pragma unroll
    for (int c = 0; c < 10; c++)
#pragma unroll
        for (int p = 0; p < 3; p++) acc[c][p] = 0ull;

    __syncthreads();

#define C1_STAGE(sarg_, bufarg_)                                               \
    do {                                                                       \
        int st_ = (sarg_);                                                     \
        if (st_ < 9) {                                                         \
            int H_ = h1 + st_ / 3 - 1, W_ = w1 + st_ % 3 - 1;                  \
            bool ok_ = ((unsigned)H_ < SS) && ((unsigned)W_ < SS);             \
            int ssz_ = ok_ ? 4 : 0;                                            \
            const float* pl_ = xb + (ok_ ? (H_ * SS + W_) * SP : 0);           \
            uint32_t d_ = sInA + (uint32_t)(bufarg_) * (1056 * 4);             \
            cpa4(d_ + sOff[0] * 4, pl_ + gOff[0], ssz_);                       \
            cpa4(d_ + sOff[1] * 4, pl_ + gOff[1], ssz_);                       \
            cpa4(d_ + sOff[2] * 4, pl_ + gOff[2], ssz_);                       \
        }                                                                      \
        cpa_commit();                                                          \
    } while (0)

    C1_STAGE(0, 0);
    C1_STAGE(1, 1);

#pragma unroll 1
    for (int to = 0; to < 9; to++) {
        cpa_wait1();
        __syncthreads();
        const float* sbuf = sIn[to & 1];
#pragma unroll
        for (int dh2 = 0; dh2 < 3; dh2++) {
            const float* row = &sbuf[(h2 + dh2) * 33 + w2_0];
            ull dup[5];
#pragma unroll
            for (int j = 0; j < 5; j++) { float v = row[j]; PACK2(dup[j], v, v); }
#pragma unroll
            for (int dw2 = 0; dw2 < 3; dw2++) {
                const ull* wp = (const ull*)(sW + (to * 9 + dh2 * 3 + dw2) * 20);
#pragma unroll
                for (int c = 0; c < 10; c++) {
                    ull w = wp[c];
#pragma unroll
                    for (int p = 0; p < 3; p++) FMA2(acc[c][p], dup[p + dw2], w);
                }
            }
        }
        __syncthreads();
        C1_STAGE(to + 2, to & 1);
    }
#undef C1_STAGE

#pragma unroll
    for (int c = 0; c < 10; c++) {
        int br = c / 5, cp = c % 5;
        float b0 = sB[2 * c], b1v = sB[2 * c + 1];
        float2* d = (float2*)g_t1 +
                    (((size_t)(b * 2 + br) * 5 + cp) * SP + h1 * SS + w1) * SP +
                    h2 * SS + w2_0;
#pragma unroll
        for (int p = 0; p < 3; p++) {
            float lo, hi;
            UNPACK2(lo, hi, acc[c][p]);
            lo += b0; hi += b1v;
            d[p] = make_float2(lo > 0.f ? lo : 0.f, hi > 0.f ? hi : 0.f);
        }
    }
}

// ---------------------------------------------------------------------------
// conv2: t1 (ci-pair float2) -> t2 (branch-interleaved), relu.
// Round-10/12 version (passed, best): 5 planes staged per to (.ca), wait0,
// static padded weights, aligned 5xLDS.128 input windows.
// ---------------------------------------------------------------------------
__global__ __launch_bounds__(300, 2)
void conv2_kernel(const float* __restrict__ b2) {
    extern __shared__ __align__(16) char sm2[];
    ull* sIn = (ull*)sm2;                       // 5 * 1088 ull
    float* sW = (float*)(sm2 + 5 * 1088 * 8);   // 9720 floats (padded)
    __shared__ float sB[10];

    int bid = blockIdx.x;
    int w1 = bid % SS;
    int t = bid / SS;
    int h1 = t % SS;
    t /= SS;
    int br = t & 1;
    int b = t >> 1;
    int tid = threadIdx.x;

    {
        const float4* src = (const float4*)(g_W2 + br * 9720);
        float4* dst = (float4*)sW;
        for (int i = tid; i < 2430; i += 300) dst[i] = src[i];
    }
    if (tid < 10) sB[tid] = b2[tid];
    for (int i = tid; i < 5440; i += 300) sIn[i] = 0ull;

    int cohalf = tid / 150;
    int r = tid % 150;
    int h2 = r / 5;
    int w2_0 = (r % 5) * 6;
    int co0 = cohalf * 5;
    int co6 = cohalf * 6;   // padded weight half offset (ull)

    // staging: plane scp = tid/60, t60 = tid%60, chunks t60 + k*60
    int scp = tid / 60;
    int t60 = tid % 60;
    int kmax = (t60 < 30) ? 8 : 7;
    uint32_t sBase = s2u(sIn) +
                     (uint32_t)(scp * 1088 + (t60 / 15 + 1) * 34 + 2 +
                                (2 * t60) % 30) * 8;
    const float2* t1f2 = (const float2*)g_t1 + (size_t)(b * 2 + br) * 5 * (size_t)S4;
    size_t gBase = (size_t)scp * S4 + 2 * t60;

    ull acc[5][6];
#pragma unroll
    for (int c = 0; c < 5; c++)
#pragma unroll
        for (int p = 0; p < 6; p++) acc[c][p] = 0ull;

#pragma unroll 1
    for (int to = 0; to < 9; to++) {
        int H = h1 + to / 3 - 1, W = w1 + to % 3 - 1;
        bool ok = ((unsigned)H < SS) && ((unsigned)W < SS);
        int srcsz = ok ? 16 : 0;
        int poff = ok ? (H * SS + W) : 0;
        __syncthreads();
        const float2* g = t1f2 + gBase + (size_t)poff * SP;
#pragma unroll
        for (int k = 0; k < 8; k++)
            if (k < kmax) cpa16(sBase + k * (136 * 8), g + k * 120, srcsz);
        cpa_commit_wait();
        __syncthreads();
#pragma unroll 1
        for (int cp = 0; cp < 5; cp++) {
            const ull* sc = sIn + cp * 1088;
            const ull* wbase = (const ull*)sW + (to * 5 + cp) * 108;
#pragma unroll
            for (int dh2 = 0; dh2 < 3; dh2++) {
                const ulonglong2* rp2 =
                    (const ulonglong2*)(sc + (h2 + dh2) * 34 + w2_0);
                ulonglong2 v0 = rp2[0], v1 = rp2[1], v2 = rp2[2], v3 = rp2[3],
                           v4 = rp2[4];
                ull aw[8] = {v0.y, v1.x, v1.y, v2.x, v2.y, v3.x, v3.y, v4.x};
#pragma unroll
                for (int dw2 = 0; dw2 < 3; dw2++) {
                    const ull* wp = wbase + (dh2 * 3 + dw2) * 12 + co6;
                    ulonglong2 wA = *(const ulonglong2*)wp;
                    ulonglong2 wB = *(const ulonglong2*)(wp + 2);
                    ull w4 = wp[4];
                    ull wv[5] = {wA.x, wA.y, wB.x, wB.y, w4};
#pragma unroll
                    for (int c = 0; c < 5; c++) {
                        ull w = wv[c];
#pragma unroll
                        for (int p = 0; p < 6; p++) FMA2(acc[c][p], aw[p + dw2], w);
                    }
                }
            }
        }
    }

    int pos0 = h2 * SS + w2_0;
#pragma unroll
    for (int c = 0; c < 5; c++) {
        int co = co0 + c;
        float bias = sB[co];
        float* d = g_t2 + ((size_t)(b * 10 + co) * SP + h1 * SS + w1) * 1800 +
                   pos0 * 2 + br;
#pragma unroll
        for (int p = 0; p < 6; p++) {
            float lo, hi;
            UNPACK2(lo, hi, acc[c][p]);     // even-ci + odd-ci partials
            float v = lo + hi + bias;
            d[2 * p] = v > 0.f ? v : 0.f;
        }
    }
}

// ---------------------------------------------------------------------------
// conv3 + final sum: t2 (10 ci, branch-interleaved float2) -> out.
// PAIRED (round-12 version, passed) with .cg staging (round-15 win).
// ---------------------------------------------------------------------------
__global__ __launch_bounds__(300, 2)
void conv3_kernel(const float* __restrict__ b3, float* __restrict__ out) {
    extern __shared__ __align__(16) char sm3[];
    ull* sD = (ull*)sm3;                        // 10 * 1088 ull
    ull* sW3 = (ull*)(sm3 + 10 * 1088 * 8);     // 810 (wA,wB)

    int bid = blockIdx.x;
    int b = bid / 450;
    int rem = bid % 450;
    int h1 = rem / 15;
    int w1b = (rem % 15) * 2;
    int tid = threadIdx.x;

    for (int i = tid; i < 810; i += 300) sW3[i] = ((const ull*)g_W3)[i];
    for (int i = tid; i < 10880; i += 300) sD[i] = 0ull;

    int P = tid / 150;          // position within pair
    int t150 = tid % 150;
    int cihalf = t150 / 75;
    int pos75 = t150 % 75;
    int h2 = (pos75 / 5) * 2;
    int w2_0 = (pos75 % 5) * 6;
    int ci0 = cihalf * 5;

    int sci = tid / 30;
    int t30 = tid % 30;
    uint32_t sBase = s2u(sD) +
                     (uint32_t)(sci * 1088 + (t30 / 15 + 1) * 34 + 2 +
                                (2 * t30) % 30) * 8;
    const float2* tb2 = (const float2*)g_t2 + (size_t)b * 10 * (size_t)S4;
    size_t gBase = (size_t)sci * S4 + 2 * t30;

    ull acc0[6], acc1[6];
#pragma unroll
    for (int p = 0; p < 6; p++) { acc0[p] = 0ull; acc1[p] = 0ull; }

#pragma unroll 1
    for (int dh1 = 0; dh1 < 3; dh1++) {
        int H = h1 + dh1 - 1;
#pragma unroll 1
        for (int i = 0; i < 4; i++) {
            int W = w1b + i - 1;
            bool ok = ((unsigned)H < SS) && ((unsigned)W < SS);
            int srcsz = ok ? 16 : 0;
            size_t poff = ok ? (size_t)(H * SS + W) * SP : 0;
            __syncthreads();
            const float2* g = tb2 + gBase + poff;
#pragma unroll
            for (int k = 0; k < 15; k++)
                cpa16cg(sBase + k * (68 * 8), g + k * 60, srcsz);
            cpa_commit_wait();
            __syncthreads();
            int dw1 = i - P;
            if ((unsigned)dw1 < 3u) {
                int to = dh1 * 3 + dw1;
#pragma unroll 1
                for (int cc = 0; cc < 5; cc++) {
                    int ci = ci0 + cc;
                    const ull* rbase = sD + ci * 1088 + h2 * 34 + w2_0;
                    const ull* wci = sW3 + (to * 10 + ci) * 9;
#pragma unroll
                    for (int rr = 0; rr < 4; rr++) {
                        const ulonglong2* rp2 =
                            (const ulonglong2*)(rbase + rr * 34);
                        ulonglong2 v0 = rp2[0], v1 = rp2[1], v2 = rp2[2],
                                   v3 = rp2[3], v4 = rp2[4];
                        ull aw[8] = {v0.y, v1.x, v1.y, v2.x,
                                     v2.y, v3.x, v3.y, v4.x};
                        if (rr < 3) {
#pragma unroll
                            for (int dw2 = 0; dw2 < 3; dw2++) {
                                ull w = wci[rr * 3 + dw2];
#pragma unroll
                                for (int p = 0; p < 6; p++)
                                    FMA2(acc0[p], aw[p + dw2], w);
                            }
                        }
                        if (rr > 0) {
#pragma unroll
                            for (int dw2 = 0; dw2 < 3; dw2++) {
                                ull w = wci[(rr - 1) * 3 + dw2];
#pragma unroll
                                for (int p = 0; p < 6; p++)
                                    FMA2(acc1[p], aw[p + dw2], w);
                            }
                        }
                    }
                }
            }
        }
    }

    // reduce ci-halves via smem (reuse sD); each position independent
    __syncthreads();
    ull* red = (ull*)sD;
    int rbase2 = (P * 75 + pos75) * 12;
    if (cihalf) {
#pragma unroll
        for (int p = 0; p < 6; p++) {
            red[rbase2 + p] = acc0[p];
            red[rbase2 + 6 + p] = acc1[p];
        }
    }
    __syncthreads();
    if (!cihalf) {
        float bv = b3[0];
        int w1p = w1b + P;
        float* dst = out + (size_t)b * S4 + (h1 * SS + w1p) * SP + h2 * SS + w2_0;
#pragma unroll
        for (int p = 0; p < 6; p++) {
            ull o0 = red[rbase2 + p];
            ull o1 = red[rbase2 + 6 + p];
            ADD2(acc0[p], acc0[p], o0);
            ADD2(acc1[p], acc1[p], o1);
            float lo, hi;
            UNPACK2(lo, hi, acc0[p]);
            float va = lo + bv, vb = hi + bv;
            va = va > 0.f ? va : 0.f;
            vb = vb > 0.f ? vb : 0.f;
            dst[p] = va + vb;
            UNPACK2(lo, hi, acc1[p]);
            va = lo + bv; vb = hi + bv;
            va = va > 0.f ? va : 0.f;
            vb = vb > 0.f ? vb : 0.f;
            dst[SS + p] = va + vb;
        }
    }
}

// ---------------------------------------------------------------------------
extern "C" void kernel_launch(void* const* d_in, const int* in_sizes, int n_in,
                              void* d_out, int out_size) {
    const float* x = (const float*)d_in[0];
    const float* w1 = (const float*)d_in[1];
    const float* b1 = (const float*)d_in[2];
    const float* w2 = (const float*)d_in[3];
    const float* b2 = (const float*)d_in[4];
    const float* w3 = (const float*)d_in[5];
    const float* b3 = (const float*)d_in[6];
    float* out = (float*)d_out;

    const int smem2 = 5 * 1088 * 8 + 9720 * 4;    // 43520 + 38880 = 82400 B
    const int smem3 = 10 * 1088 * 8 + 810 * 8;    // 93520 B
    cudaFuncSetAttribute(conv2_kernel,
                         cudaFuncAttributeMaxDynamicSharedMemorySize, smem2);
    cudaFuncSetAttribute(conv3_kernel,
                         cudaFuncAttributeMaxDynamicSharedMemorySize, smem3);

    prep_kernel<<<32, 256>>>(w1, w2, w3);
    conv1_kernel<<<NB * SP, 300>>>(x, b1);
    conv2_kernel<<<NB * 2 * SP, 300, smem2>>>(b2);
    conv3_kernel<<<NB * 450, 300, smem3>>>(b3, out);
}

// round 17
// speedup vs baseline: 1.3276x; 1.0049x over previous
#include <cuda_runtime.h>
#include <cstdint>

#define SS 30
#define SP 900          // 30*30
#define S4 810000       // 30^4
#define NB 2

typedef unsigned long long ull;

// t1: [b][br][cipair5][h1w1][pos][2]  (lanes = ci even/odd)  — float2 elements
__device__ __align__(16) float g_t1[NB * 2 * 5 * SP * SP * 2];
// t2: [b][co10][h1w1][pos][br2]  — float2 elements (lanes = branch A/B)
__device__ __align__(16) float g_t2[NB * 10 * SP * SP * 2];
// Weights
__device__ __align__(16) float g_W1[9 * 9 * 20];                 // [to][ti][co20]
// W2: [br][to][cp][ti][cohalf][co5+pad][ci-lane]  (12 ull per tap, 16B-aligned)
__device__ __align__(16) float g_W2[2 * 9 * 5 * 9 * 12 * 2];
__device__ __align__(16) float g_W3[9 * 10 * 9 * 2];             // [to][ci][ti][br2]

#define PACK2(d, a, b)  asm("mov.b64 %0, {%1, %2};" : "=l"(d) : "f"(a), "f"(b))
#define FMA2(d, a, b)   asm("fma.rn.f32x2 %0, %1, %2, %0;" : "+l"(d) : "l"(a), "l"(b))
#define ADD2(d, a, b)   asm("add.rn.f32x2 %0, %1, %2;" : "=l"(d) : "l"(a), "l"(b))
#define UNPACK2(lo, hi, d) asm("mov.b64 {%0, %1}, %2;" : "=f"(lo), "=f"(hi) : "l"(d))

__device__ __forceinline__ uint32_t s2u(const void* p) {
    uint32_t a;
    asm("{ .reg .u64 t; cvta.to.shared.u64 t, %1; cvt.u32.u64 %0, t; }"
        : "=r"(a) : "l"(p));
    return a;
}
__device__ __forceinline__ void cpa4(uint32_t s, const void* g, int srcsz) {
    asm volatile("cp.async.ca.shared.global [%0], [%1], 4, %2;"
                 :: "r"(s), "l"(g), "r"(srcsz));
}
// .ca flavor — conv2 staging (L1 allocation helps; R12-verified)
__device__ __forceinline__ void cpa16(uint32_t s, const void* g, int srcsz) {
    asm volatile("cp.async.ca.shared.global [%0], [%1], 16, %2;"
                 :: "r"(s), "l"(g), "r"(srcsz));
}
// .cg flavor — conv3 staging (L1 bypass; R15-verified win for conv3)
__device__ __forceinline__ void cpa16cg(uint32_t s, const void* g, int srcsz) {
    asm volatile("cp.async.cg.shared.global [%0], [%1], 16, %2;"
                 :: "r"(s), "l"(g), "r"(srcsz));
}
__device__ __forceinline__ void cpa_commit() {
    asm volatile("cp.async.commit_group;");
}
__device__ __forceinline__ void cpa_commit_wait() {
    asm volatile("cp.async.commit_group;");
    asm volatile("cp.async.wait_group 0;" ::: "memory");
}
__device__ __forceinline__ void cpa_wait1() {
    asm volatile("cp.async.wait_group 1;" ::: "memory");
}

// ---------------------------------------------------------------------------
// Weight prep.
// ---------------------------------------------------------------------------
__global__ void prep_kernel(const float* __restrict__ w1,
                            const float* __restrict__ w2,
                            const float* __restrict__ w3) {
    int tid = blockIdx.x * blockDim.x + threadIdx.x;
    int stride = gridDim.x * blockDim.x;
    for (int i = tid; i < 9 * 9 * 20; i += stride) {
        int co = i % 20;
        int ti = (i / 20) % 9;
        int to = i / 180;
        g_W1[i] = (co < 10) ? w1[co * 81 + to * 9 + ti]
                            : w1[(co - 10) * 81 + ti * 9 + to];
    }
    // W2 padded: j = [br][to][cp][ti][half][co6], lane = ci parity
    for (int i = tid; i < 19440; i += stride) {
        int lane = i & 1;
        int j = i >> 1;
        int co6 = j % 6;
        int half = (j / 6) % 2;
        int ti = (j / 12) % 9;
        int cp = (j / 108) % 5;
        int to = (j / 540) % 9;
        int br = j / 4860;
        float v = 0.f;
        if (co6 < 5) {
            int co = half * 5 + co6;
            int ci = 2 * cp + lane;
            int tap = br ? (ti * 9 + to) : (to * 9 + ti);
            v = w2[(co * 10 + ci) * 81 + tap];
        }
        g_W2[i] = v;
    }
    for (int i = tid; i < 1620; i += stride) {
        int br = i % 2;
        int ti = (i / 2) % 9;
        int ci = (i / 18) % 10;
        int to = i / 180;
        g_W3[i] = (br == 0) ? w3[ci * 81 + to * 9 + ti]
                            : w3[ci * 81 + ti * 9 + to];
    }
}

// ---------------------------------------------------------------------------
// conv1: x (1 ch) -> t1 (ci-pair interleaved), relu.  One CTA per (b,h1,w1).
// Double-buffered plane staging (round-10 version, passed).
// ---------------------------------------------------------------------------
__global__ __launch_bounds__(300)
void conv1_kernel(const float* __restrict__ x, const float* __restrict__ b1) {
    __shared__ __align__(16) float sIn[2][32 * 33];
    __shared__ __align__(16) float sW[9 * 9 * 20];
    __shared__ float sB[20];
    int bid = blockIdx.x;
    int b = bid / SP;
    int rem = bid % SP;
    int h1 = rem / SS, w1 = rem % SS;
    int tid = threadIdx.x;

    {
        const float4* src = (const float4*)g_W1;
        float4* dst = (float4*)sW;
        for (int i = tid; i < 405; i += 300) dst[i] = src[i];
    }
    if (tid < 20) sB[tid] = b1[tid % 10];
    for (int i = tid; i < 2 * 32 * 33; i += 300) ((float*)sIn)[i] = 0.f;

    int h2 = tid / 10;
    int w2_0 = (tid % 10) * 3;

    int gOff[3], sOff[3];
#pragma unroll
    for (int k = 0; k < 3; k++) {
        int j = tid + k * 300;
        int rr = j / SS, cc = j % SS;
        gOff[k] = j;
        sOff[k] = (rr + 1) * 33 + cc + 1;
    }
    uint32_t sInA = s2u(sIn);
    const float* xb = x + (size_t)b * S4;

    ull acc[10][3];
#pragma unroll
    for (int c = 0; c < 10; c++)
#pragma unroll
        for (int p = 0; p < 3; p++) acc[c][p] = 0ull;

    __syncthreads();

#define C1_STAGE(sarg_, bufarg_)                                               \
    do {                                                                       \
        int st_ = (sarg_);                                                     \
        if (st_ < 9) {                                                         \
            int H_ = h1 + st_ / 3 - 1, W_ = w1 + st_ % 3 - 1;                  \
            bool ok_ = ((unsigned)H_ < SS) && ((unsigned)W_ < SS);             \
            int ssz_ = ok_ ? 4 : 0;                                            \
            const float* pl_ = xb + (ok_ ? (H_ * SS + W_) * SP : 0);           \
            uint32_t d_ = sInA + (uint32_t)(bufarg_) * (1056 * 4);             \
            cpa4(d_ + sOff[0] * 4, pl_ + gOff[0], ssz_);                       \
            cpa4(d_ + sOff[1] * 4, pl_ + gOff[1], ssz_);                       \
            cpa4(d_ + sOff[2] * 4, pl_ + gOff[2], ssz_);                       \
        }                                                                      \
        cpa_commit();                                                          \
    } while (0)

    C1_STAGE(0, 0);
    C1_STAGE(1, 1);

#pragma unroll 1
    for (int to = 0; to < 9; to++) {
        cpa_wait1();
        __syncthreads();
        const float* sbuf = sIn[to & 1];
#pragma unroll
        for (int dh2 = 0; dh2 < 3; dh2++) {
            const float* row = &sbuf[(h2 + dh2) * 33 + w2_0];
            ull dup[5];
#pragma unroll
            for (int j = 0; j < 5; j++) { float v = row[j]; PACK2(dup[j], v, v); }
#pragma unroll
            for (int dw2 = 0; dw2 < 3; dw2++) {
                const ull* wp = (const ull*)(sW + (to * 9 + dh2 * 3 + dw2) * 20);
#pragma unroll
                for (int c = 0; c < 10; c++) {
                    ull w = wp[c];
#pragma unroll
                    for (int p = 0; p < 3; p++) FMA2(acc[c][p], dup[p + dw2], w);
                }
            }
        }
        __syncthreads();
        C1_STAGE(to + 2, to & 1);
    }
#undef C1_STAGE

#pragma unroll
    for (int c = 0; c < 10; c++) {
        int br = c / 5, cp = c % 5;
        float b0 = sB[2 * c], b1v = sB[2 * c + 1];
        float2* d = (float2*)g_t1 +
                    (((size_t)(b * 2 + br) * 5 + cp) * SP + h1 * SS + w1) * SP +
                    h2 * SS + w2_0;
#pragma unroll
        for (int p = 0; p < 3; p++) {
            float lo, hi;
            UNPACK2(lo, hi, acc[c][p]);
            lo += b0; hi += b1v;
            d[p] = make_float2(lo > 0.f ? lo : 0.f, hi > 0.f ? hi : 0.f);
        }
    }
}

// ---------------------------------------------------------------------------
// conv2: t1 (ci-pair float2) -> t2 (branch-interleaved), relu.
// Round-10/12 version (passed, best): 5 planes staged per to (.ca), wait0,
// static padded weights, aligned 5xLDS.128 input windows.
// ---------------------------------------------------------------------------
__global__ __launch_bounds__(300, 2)
void conv2_kernel(const float* __restrict__ b2) {
    extern __shared__ __align__(16) char sm2[];
    ull* sIn = (ull*)sm2;                       // 5 * 1088 ull
    float* sW = (float*)(sm2 + 5 * 1088 * 8);   // 9720 floats (padded)
    __shared__ float sB[10];

    int bid = blockIdx.x;
    int w1 = bid % SS;
    int t = bid / SS;
    int h1 = t % SS;
    t /= SS;
    int br = t & 1;
    int b = t >> 1;
    int tid = threadIdx.x;

    {
        const float4* src = (const float4*)(g_W2 + br * 9720);
        float4* dst = (float4*)sW;
        for (int i = tid; i < 2430; i += 300) dst[i] = src[i];
    }
    if (tid < 10) sB[tid] = b2[tid];
    for (int i = tid; i < 5440; i += 300) sIn[i] = 0ull;

    int cohalf = tid / 150;
    int r = tid % 150;
    int h2 = r / 5;
    int w2_0 = (r % 5) * 6;
    int co0 = cohalf * 5;
    int co6 = cohalf * 6;   // padded weight half offset (ull)

    // staging: plane scp = tid/60, t60 = tid%60, chunks t60 + k*60
    int scp = tid / 60;
    int t60 = tid % 60;
    int kmax = (t60 < 30) ? 8 : 7;
    uint32_t sBase = s2u(sIn) +
                     (uint32_t)(scp * 1088 + (t60 / 15 + 1) * 34 + 2 +
                                (2 * t60) % 30) * 8;
    const float2* t1f2 = (const float2*)g_t1 + (size_t)(b * 2 + br) * 5 * (size_t)S4;
    size_t gBase = (size_t)scp * S4 + 2 * t60;

    ull acc[5][6];
#pragma unroll
    for (int c = 0; c < 5; c++)
#pragma unroll
        for (int p = 0; p < 6; p++) acc[c][p] = 0ull;

#pragma unroll 1
    for (int to = 0; to < 9; to++) {
        int H = h1 + to / 3 - 1, W = w1 + to % 3 - 1;
        bool ok = ((unsigned)H < SS) && ((unsigned)W < SS);
        int srcsz = ok ? 16 : 0;
        int poff = ok ? (H * SS + W) : 0;
        __syncthreads();
        const float2* g = t1f2 + gBase + (size_t)poff * SP;
#pragma unroll
        for (int k = 0; k < 8; k++)
            if (k < kmax) cpa16(sBase + k * (136 * 8), g + k * 120, srcsz);
        cpa_commit_wait();
        __syncthreads();
#pragma unroll 1
        for (int cp = 0; cp < 5; cp++) {
            const ull* sc = sIn + cp * 1088;
            const ull* wbase = (const ull*)sW + (to * 5 + cp) * 108;
#pragma unroll
            for (int dh2 = 0; dh2 < 3; dh2++) {
                const ulonglong2* rp2 =
                    (const ulonglong2*)(sc + (h2 + dh2) * 34 + w2_0);
                ulonglong2 v0 = rp2[0], v1 = rp2[1], v2 = rp2[2], v3 = rp2[3],
                           v4 = rp2[4];
                ull aw[8] = {v0.y, v1.x, v1.y, v2.x, v2.y, v3.x, v3.y, v4.x};
#pragma unroll
                for (int dw2 = 0; dw2 < 3; dw2++) {
                    const ull* wp = wbase + (dh2 * 3 + dw2) * 12 + co6;
                    ulonglong2 wA = *(const ulonglong2*)wp;
                    ulonglong2 wB = *(const ulonglong2*)(wp + 2);
                    ull w4 = wp[4];
                    ull wv[5] = {wA.x, wA.y, wB.x, wB.y, w4};
#pragma unroll
                    for (int c = 0; c < 5; c++) {
                        ull w = wv[c];
#pragma unroll
                        for (int p = 0; p < 6; p++) FMA2(acc[c][p], aw[p + dw2], w);
                    }
                }
            }
        }
    }

    int pos0 = h2 * SS + w2_0;
#pragma unroll
    for (int c = 0; c < 5; c++) {
        int co = co0 + c;
        float bias = sB[co];
        float* d = g_t2 + ((size_t)(b * 10 + co) * SP + h1 * SS + w1) * 1800 +
                   pos0 * 2 + br;
#pragma unroll
        for (int p = 0; p < 6; p++) {
            float lo, hi;
            UNPACK2(lo, hi, acc[c][p]);     // even-ci + odd-ci partials
            float v = lo + hi + bias;
            d[2 * p] = v > 0.f ? v : 0.f;
        }
    }
}

// ---------------------------------------------------------------------------
// conv3 + final sum: t2 (10 ci, branch-interleaved float2) -> out.
// 2x2 TILED: one CTA per (b, h1-pair, w1-pair).  300 threads =
// P(4 = ph x pw) x 75.  Steps: 4 H x 4 W = 16 staged planes for 4 outputs
// (4/output vs 6/output in the pair version).  Each thread owns ALL 10 ci
// for its 2h2 x 6w2 tile -> no cihalf reduction, direct GMEM write.
// .cg staging (round-15 win).
// ---------------------------------------------------------------------------
__global__ __launch_bounds__(300, 2)
void conv3_kernel(const float* __restrict__ b3, float* __restrict__ out) {
    extern __shared__ __align__(16) char sm3[];
    ull* sD = (ull*)sm3;                        // 10 * 1088 ull
    ull* sW3 = (ull*)(sm3 + 10 * 1088 * 8);     // 810 (wA,wB)

    int bid = blockIdx.x;
    int b = bid / 225;
    int rem = bid % 225;
    int h1b = (rem / 15) * 2;
    int w1b = (rem % 15) * 2;
    int tid = threadIdx.x;

    for (int i = tid; i < 810; i += 300) sW3[i] = ((const ull*)g_W3)[i];
    for (int i = tid; i < 10880; i += 300) sD[i] = 0ull;

    int P = tid / 75;           // output position within 2x2 tile
    int ph = P >> 1, pw = P & 1;
    int pos75 = tid % 75;
    int h2 = (pos75 / 5) * 2;
    int w2_0 = (pos75 % 5) * 6;

    // staging: 30 threads per plane; plane sci = tid/30, t30 = tid%30;
    // chunk c = t30 + 30k (k<15): f2 off 2c, row 2k + t30/15, col (2t30)%30.
    int sci = tid / 30;
    int t30 = tid % 30;
    uint32_t sBase = s2u(sD) +
                     (uint32_t)(sci * 1088 + (t30 / 15 + 1) * 34 + 2 +
                                (2 * t30) % 30) * 8;
    const float2* tb2 = (const float2*)g_t2 + (size_t)b * 10 * (size_t)S4;
    size_t gBase = (size_t)sci * S4 + 2 * t30;

    ull acc0[6], acc1[6];
#pragma unroll
    for (int p = 0; p < 6; p++) { acc0[p] = 0ull; acc1[p] = 0ull; }

#pragma unroll 1
    for (int iH = 0; iH < 4; iH++) {
        int H = h1b + iH - 1;
#pragma unroll 1
        for (int iW = 0; iW < 4; iW++) {
            int W = w1b + iW - 1;
            bool ok = ((unsigned)H < SS) && ((unsigned)W < SS);
            int srcsz = ok ? 16 : 0;
            size_t poff = ok ? (size_t)(H * SS + W) * SP : 0;
            __syncthreads();
            const float2* g = tb2 + gBase + poff;
#pragma unroll
            for (int k = 0; k < 15; k++)
                cpa16cg(sBase + k * (68 * 8), g + k * 60, srcsz);
            cpa_commit_wait();
            __syncthreads();
            int dh1 = iH - ph;
            int dw1 = iW - pw;
            if (((unsigned)dh1 < 3u) && ((unsigned)dw1 < 3u)) {
                int to = dh1 * 3 + dw1;
#pragma unroll 1
                for (int ci = 0; ci < 10; ci++) {
                    const ull* rbase = sD + ci * 1088 + h2 * 34 + w2_0;
                    const ull* wci = sW3 + (to * 10 + ci) * 9;
#pragma unroll
                    for (int rr = 0; rr < 4; rr++) {
                        const ulonglong2* rp2 =
                            (const ulonglong2*)(rbase + rr * 34);
                        ulonglong2 v0 = rp2[0], v1 = rp2[1], v2 = rp2[2],
                                   v3 = rp2[3], v4 = rp2[4];
                        ull aw[8] = {v0.y, v1.x, v1.y, v2.x,
                                     v2.y, v3.x, v3.y, v4.x};
                        if (rr < 3) {
#pragma unroll
                            for (int dw2 = 0; dw2 < 3; dw2++) {
                                ull w = wci[rr * 3 + dw2];
#pragma unroll
                                for (int p = 0; p < 6; p++)
                                    FMA2(acc0[p], aw[p + dw2], w);
                            }
                        }
                        if (rr > 0) {
#pragma unroll
                            for (int dw2 = 0; dw2 < 3; dw2++) {
                                ull w = wci[(rr - 1) * 3 + dw2];
#pragma unroll
                                for (int p = 0; p < 6; p++)
                                    FMA2(acc1[p], aw[p + dw2], w);
                            }
                        }
                    }
                }
            }
        }
    }

    // direct output: each thread fully owns its outputs (no reduction)
    float bv = b3[0];
    int h1p = h1b + ph;
    int w1p = w1b + pw;
    float* dst = out + (size_t)b * S4 + (h1p * SS + w1p) * SP + h2 * SS + w2_0;
#pragma unroll
    for (int p = 0; p < 6; p++) {
        float lo, hi;
        UNPACK2(lo, hi, acc0[p]);
        float va = lo + bv, vb = hi + bv;
        va = va > 0.f ? va : 0.f;
        vb = vb > 0.f ? vb : 0.f;
        dst[p] = va + vb;
        UNPACK2(lo, hi, acc1[p]);
        va = lo + bv; vb = hi + bv;
        va = va > 0.f ? va : 0.f;
        vb = vb > 0.f ? vb : 0.f;
        dst[SS + p] = va + vb;
    }
}

// ---------------------------------------------------------------------------
extern "C" void kernel_launch(void* const* d_in, const int* in_sizes, int n_in,
                              void* d_out, int out_size) {
    const float* x = (const float*)d_in[0];
    const float* w1 = (const float*)d_in[1];
    const float* b1 = (const float*)d_in[2];
    const float* w2 = (const float*)d_in[3];
    const float* b2 = (const float*)d_in[4];
    const float* w3 = (const float*)d_in[5];
    const float* b3 = (const float*)d_in[6];
    float* out = (float*)d_out;

    const int smem2 = 5 * 1088 * 8 + 9720 * 4;    // 43520 + 38880 = 82400 B
    const int smem3 = 10 * 1088 * 8 + 810 * 8;    // 93520 B
    cudaFuncSetAttribute(conv2_kernel,
                         cudaFuncAttributeMaxDynamicSharedMemorySize, smem2);
    cudaFuncSetAttribute(conv3_kernel,
                         cudaFuncAttributeMaxDynamicSharedMemorySize, smem3);

    prep_kernel<<<32, 256>>>(w1, w2, w3);
    conv1_kernel<<<NB * SP, 300>>>(x, b1);
    conv2_kernel<<<NB * 2 * SP, 300, smem2>>>(b2);
    conv3_kernel<<<NB * 225, 300, smem3>>>(b3, out);
}